// round 11
// baseline (speedup 1.0000x reference)
#include <cuda_runtime.h>
#include <cstdint>

// B=2048, D=3706, total=B*D=7,589,888 (divisible by 256)
// inputs: d_in[0] fake [B,D] f32; d_in[1] minb [D] f32; d_in[2] lens [D,4] f32
// output: dist f32 [B,D,6] then val f32 [B,D]
//
// b0=min[d]; b_{k+1}=b_k+relu(len[d,k])+1e-4 (strictly increasing)
// dist[r] = (r==0 || a>b[r-1]) && (r==5 || a<b[r]); a==b_k -> all zeros
// val = sum r*dist[r]
//
// R11 = R10 (== R4 + magic div; 37.3us, at the HBM write wall) with one
// change: output stores use __stwt (write-through) instead of __stcs, probing
// whether bypassing L2 dirty-line allocation shortens the write drain. Store
// shape unchanged: warp-coalesced float4 -> full 128B line per instruction,
// so sector coverage stays complete (no R5-style partial-sector penalty).
// fake stays default-policy -> L2-resident across graph replays.

#define EPSK 1e-4f
#define TPB 256
#define MAGIC_K 40

__global__ void __launch_bounds__(TPB)
discret_kernel(const float* __restrict__ fake,
               const float* __restrict__ minb,
               const float4* __restrict__ lens,
               float* __restrict__ out_dist,   // [B*D*6]
               float* __restrict__ out_val,    // [B*D]
               int total, unsigned D,
               unsigned long long magic)
{
    __shared__ float sdist[TPB * 6];   // 6 KB

    int t   = threadIdx.x;
    int idx = blockIdx.x * TPB + t;

    float d0 = 0.f, d1 = 0.f, d2 = 0.f, d3 = 0.f, d4 = 0.f, d5 = 0.f;

    if (idx < total) {
        // d = idx - D*floor(idx/D) via exact magic multiply
        unsigned x = (unsigned)idx;
        unsigned q = (unsigned)(((unsigned long long)x * magic) >> MAGIC_K);
        unsigned d = x - q * D;

        float a  = fake[idx];              // default policy: L2-resident across replays
        float4 L = __ldg(&lens[d]);
        float b0 = __ldg(&minb[d]);
        float b1 = b0 + fmaxf(L.x, 0.0f) + EPSK;
        float b2 = b1 + fmaxf(L.y, 0.0f) + EPSK;
        float b3 = b2 + fmaxf(L.z, 0.0f) + EPSK;
        float b4 = b3 + fmaxf(L.w, 0.0f) + EPSK;

        d0 = (a < b0)           ? 1.0f : 0.0f;
        d1 = (a > b0 && a < b1) ? 1.0f : 0.0f;
        d2 = (a > b1 && a < b2) ? 1.0f : 0.0f;
        d3 = (a > b2 && a < b3) ? 1.0f : 0.0f;
        d4 = (a > b3 && a < b4) ? 1.0f : 0.0f;
        d5 = (a > b4)           ? 1.0f : 0.0f;

        float v = d1 + 2.0f * d2 + 3.0f * d3 + 4.0f * d4 + 5.0f * d5;
        __stwt(&out_val[idx], v);          // EARLY store, write-through
    }

    // stage into smem (stride-6 word writes: benign 2-way bank conflict)
    float* s = sdist + t * 6;
    s[0] = d0; s[1] = d1; s[2] = d2; s[3] = d3; s[4] = d4; s[5] = d5;
    __syncthreads();

    int block_first = blockIdx.x * TPB;
    int n_valid = total - block_first;
    if (n_valid >= TPB) {
        // full block: flush 1536 floats = 384 float4, fully coalesced, write-through
        const float4* s4 = reinterpret_cast<const float4*>(sdist);
        float4* g4 = reinterpret_cast<float4*>(out_dist + (size_t)block_first * 6);
        #pragma unroll
        for (int i = t; i < (TPB * 6) / 4; i += TPB)
            __stwt(&g4[i], s4[i]);
    } else {
        // tail block (unused for this shape, kept for generality)
        float* g = out_dist + (size_t)block_first * 6;
        for (int i = t; i < n_valid * 6; i += TPB)
            __stwt(&g[i], sdist[i]);
    }
}

extern "C" void kernel_launch(void* const* d_in, const int* in_sizes, int n_in,
                              void* d_out, int out_size)
{
    const float*  fake = (const float*)d_in[0];
    const float*  minb = (const float*)d_in[1];
    const float4* lens = (const float4*)d_in[2];

    int total  = in_sizes[0];          // B*D
    unsigned D = (unsigned)in_sizes[1];

    // magic = floor(2^40/D) + 1 ; exact q for all x in range (see header)
    unsigned long long magic = ((1ull << MAGIC_K) / D) + 1ull;

    float* out  = (float*)d_out;
    float* dist = out;                          // [B*D*6]
    float* val  = out + (size_t)total * 6;      // [B*D]

    int blocks = (total + TPB - 1) / TPB;
    discret_kernel<<<blocks, TPB>>>(fake, minb, lens, dist, val, total, D, magic);
}

// round 12
// speedup vs baseline: 1.1902x; 1.1902x over previous
#include <cuda_runtime.h>
#include <cstdint>

// B=2048, D=3706, total=B*D=7,589,888 (divisible by 256)
// inputs: d_in[0] fake [B,D] f32; d_in[1] minb [D] f32; d_in[2] lens [D,4] f32
// output: dist f32 [B,D,6] then val f32 [B,D]
//
// b0=min[d]; b_{k+1}=b_k+relu(len[d,k])+1e-4 (strictly increasing)
// dist[r] = (r==0 || a>b[r-1]) && (r==5 || a<b[r]); a==b_k -> all zeros
// val = sum r*dist[r]
//
// FINAL (== R10, best at 37.3us). The R0-R11 sweep established this kernel is
// pinned at the HBM write-drain wall (212MB writes @ ~5.7TB/s). Load-bearing
// choices, each validated by a controlled experiment:
//   - __stcs (evict-first, write-back) on ALL output stores: +13% (R4).
//     __stwt regressed 16% (R11); default policy loses inter-replay L2
//     residency of fake (R1/R2).
//   - fake read with DEFAULT policy -> stays L2-resident across graph
//     replays (__ldcs destroyed this, R3).
//   - TPB=256, 1 element/thread (512 and 4/thread both regressed).
//   - smem-staged dist flushed as warp-coalesced float4 (full 128B line per
//     warp-instruction; required for evict-first lines to merge cleanly).
//   - early per-thread val store overlapping compute (late bunched flush
//     regressed, R9).
//   - idx % D via exact magic division: magic = floor(2^40/D)+1, exact for
//     x < 2^40/D ~ 2.97e8 >> total (validated rel_err=0, R9/R10).

#define EPSK 1e-4f
#define TPB 256
#define MAGIC_K 40

__global__ void __launch_bounds__(TPB)
discret_kernel(const float* __restrict__ fake,
               const float* __restrict__ minb,
               const float4* __restrict__ lens,
               float* __restrict__ out_dist,   // [B*D*6]
               float* __restrict__ out_val,    // [B*D]
               int total, unsigned D,
               unsigned long long magic)
{
    __shared__ float sdist[TPB * 6];   // 6 KB

    int t   = threadIdx.x;
    int idx = blockIdx.x * TPB + t;

    float d0 = 0.f, d1 = 0.f, d2 = 0.f, d3 = 0.f, d4 = 0.f, d5 = 0.f;

    if (idx < total) {
        // d = idx - D*floor(idx/D) via exact magic multiply
        unsigned x = (unsigned)idx;
        unsigned q = (unsigned)(((unsigned long long)x * magic) >> MAGIC_K);
        unsigned d = x - q * D;

        float a  = fake[idx];              // default policy: L2-resident across replays
        float4 L = __ldg(&lens[d]);
        float b0 = __ldg(&minb[d]);
        float b1 = b0 + fmaxf(L.x, 0.0f) + EPSK;
        float b2 = b1 + fmaxf(L.y, 0.0f) + EPSK;
        float b3 = b2 + fmaxf(L.z, 0.0f) + EPSK;
        float b4 = b3 + fmaxf(L.w, 0.0f) + EPSK;

        d0 = (a < b0)           ? 1.0f : 0.0f;
        d1 = (a > b0 && a < b1) ? 1.0f : 0.0f;
        d2 = (a > b1 && a < b2) ? 1.0f : 0.0f;
        d3 = (a > b2 && a < b3) ? 1.0f : 0.0f;
        d4 = (a > b3 && a < b4) ? 1.0f : 0.0f;
        d5 = (a > b4)           ? 1.0f : 0.0f;

        float v = d1 + 2.0f * d2 + 3.0f * d3 + 4.0f * d4 + 5.0f * d5;
        __stcs(&out_val[idx], v);          // early store, overlaps compute
    }

    // stage into smem (stride-6 word writes: benign 2-way bank conflict)
    float* s = sdist + t * 6;
    s[0] = d0; s[1] = d1; s[2] = d2; s[3] = d3; s[4] = d4; s[5] = d5;
    __syncthreads();

    int block_first = blockIdx.x * TPB;
    int n_valid = total - block_first;
    if (n_valid >= TPB) {
        // full block: flush 1536 floats = 384 float4, fully coalesced, evict-first
        const float4* s4 = reinterpret_cast<const float4*>(sdist);
        float4* g4 = reinterpret_cast<float4*>(out_dist + (size_t)block_first * 6);
        #pragma unroll
        for (int i = t; i < (TPB * 6) / 4; i += TPB)
            __stcs(&g4[i], s4[i]);
    } else {
        // tail block (unused for this shape, kept for generality)
        float* g = out_dist + (size_t)block_first * 6;
        for (int i = t; i < n_valid * 6; i += TPB)
            __stcs(&g[i], sdist[i]);
    }
}

extern "C" void kernel_launch(void* const* d_in, const int* in_sizes, int n_in,
                              void* d_out, int out_size)
{
    const float*  fake = (const float*)d_in[0];
    const float*  minb = (const float*)d_in[1];
    const float4* lens = (const float4*)d_in[2];

    int total  = in_sizes[0];          // B*D
    unsigned D = (unsigned)in_sizes[1];

    // magic = floor(2^40/D) + 1 ; exact q for all x in range (see header)
    unsigned long long magic = ((1ull << MAGIC_K) / D) + 1ull;

    float* out  = (float*)d_out;
    float* dist = out;                          // [B*D*6]
    float* val  = out + (size_t)total * 6;      // [B*D]

    int blocks = (total + TPB - 1) / TPB;
    discret_kernel<<<blocks, TPB>>>(fake, minb, lens, dist, val, total, D, magic);
}

// round 13
// speedup vs baseline: 1.2026x; 1.0104x over previous
#include <cuda_runtime.h>
#include <cstdint>

// B=2048, D=3706, total=B*D=7,589,888 (divisible by 256)
// inputs: d_in[0] fake [B,D] f32; d_in[1] minb [D] f32; d_in[2] lens [D,4] f32
// output: dist f32 [B,D,6] then val f32 [B,D]
//
// b0=min[d]; b_{k+1}=b_k+relu(len[d,k])+1e-4 (strictly increasing)
// dist[r] = (r==0 || a>b[r-1]) && (r==5 || a<b[r]); a==b_k -> all zeros
// val = sum r*dist[r]
//
// FINAL (R10/R12, reproducibly 37.3us). Pinned at the HBM write-drain wall
// (212MB writes @ ~5.7TB/s ~ 71% of spec). Load-bearing choices, each
// validated by a controlled experiment across rounds R0-R12:
//   - __stcs (evict-first, write-back) on ALL output stores: +13% (R4).
//     __stwt regressed 16% (R11); default policy loses inter-replay L2
//     residency of fake (R1/R2).
//   - fake read with DEFAULT policy -> stays L2-resident across graph
//     replays (__ldcs destroyed this, R3).
//   - TPB=256, 1 element/thread (512 threads and 4 elems/thread both
//     regressed: R7, R3).
//   - smem-staged dist flushed as warp-coalesced float4 (full 128B line per
//     warp-instruction; evict-first lines merge cleanly).
//   - early per-thread val store overlapping compute (late bunched flush
//     regressed, R9).
//   - idx % D via exact magic division: magic = floor(2^40/D)+1, exact for
//     x < 2^40/D ~ 2.97e8 >> total (validated rel_err=0, R9/R10/R12).
//   - store shape/engine proven non-binding: LDS+STG == TMA bulk == scatter
//     within 2% (R1/R2/R5/R6/R7).

#define EPSK 1e-4f
#define TPB 256
#define MAGIC_K 40

__global__ void __launch_bounds__(TPB)
discret_kernel(const float* __restrict__ fake,
               const float* __restrict__ minb,
               const float4* __restrict__ lens,
               float* __restrict__ out_dist,   // [B*D*6]
               float* __restrict__ out_val,    // [B*D]
               int total, unsigned D,
               unsigned long long magic)
{
    __shared__ float sdist[TPB * 6];   // 6 KB

    int t   = threadIdx.x;
    int idx = blockIdx.x * TPB + t;

    float d0 = 0.f, d1 = 0.f, d2 = 0.f, d3 = 0.f, d4 = 0.f, d5 = 0.f;

    if (idx < total) {
        // d = idx - D*floor(idx/D) via exact magic multiply
        unsigned x = (unsigned)idx;
        unsigned q = (unsigned)(((unsigned long long)x * magic) >> MAGIC_K);
        unsigned d = x - q * D;

        float a  = fake[idx];              // default policy: L2-resident across replays
        float4 L = __ldg(&lens[d]);
        float b0 = __ldg(&minb[d]);
        float b1 = b0 + fmaxf(L.x, 0.0f) + EPSK;
        float b2 = b1 + fmaxf(L.y, 0.0f) + EPSK;
        float b3 = b2 + fmaxf(L.z, 0.0f) + EPSK;
        float b4 = b3 + fmaxf(L.w, 0.0f) + EPSK;

        d0 = (a < b0)           ? 1.0f : 0.0f;
        d1 = (a > b0 && a < b1) ? 1.0f : 0.0f;
        d2 = (a > b1 && a < b2) ? 1.0f : 0.0f;
        d3 = (a > b2 && a < b3) ? 1.0f : 0.0f;
        d4 = (a > b3 && a < b4) ? 1.0f : 0.0f;
        d5 = (a > b4)           ? 1.0f : 0.0f;

        float v = d1 + 2.0f * d2 + 3.0f * d3 + 4.0f * d4 + 5.0f * d5;
        __stcs(&out_val[idx], v);          // early store, overlaps compute
    }

    // stage into smem (stride-6 word writes: benign 2-way bank conflict)
    float* s = sdist + t * 6;
    s[0] = d0; s[1] = d1; s[2] = d2; s[3] = d3; s[4] = d4; s[5] = d5;
    __syncthreads();

    int block_first = blockIdx.x * TPB;
    int n_valid = total - block_first;
    if (n_valid >= TPB) {
        // full block: flush 1536 floats = 384 float4, fully coalesced, evict-first
        const float4* s4 = reinterpret_cast<const float4*>(sdist);
        float4* g4 = reinterpret_cast<float4*>(out_dist + (size_t)block_first * 6);
        #pragma unroll
        for (int i = t; i < (TPB * 6) / 4; i += TPB)
            __stcs(&g4[i], s4[i]);
    } else {
        // tail block (unused for this shape, kept for generality)
        float* g = out_dist + (size_t)block_first * 6;
        for (int i = t; i < n_valid * 6; i += TPB)
            __stcs(&g[i], sdist[i]);
    }
}

extern "C" void kernel_launch(void* const* d_in, const int* in_sizes, int n_in,
                              void* d_out, int out_size)
{
    const float*  fake = (const float*)d_in[0];
    const float*  minb = (const float*)d_in[1];
    const float4* lens = (const float4*)d_in[2];

    int total  = in_sizes[0];          // B*D
    unsigned D = (unsigned)in_sizes[1];

    // magic = floor(2^40/D) + 1 ; exact q for all x in range (see header)
    unsigned long long magic = ((1ull << MAGIC_K) / D) + 1ull;

    float* out  = (float*)d_out;
    float* dist = out;                          // [B*D*6]
    float* val  = out + (size_t)total * 6;      // [B*D]

    int blocks = (total + TPB - 1) / TPB;
    discret_kernel<<<blocks, TPB>>>(fake, minb, lens, dist, val, total, D, magic);
}